// round 10
// baseline (speedup 1.0000x reference)
#include <cuda_runtime.h>
#include <cuda_fp16.h>
#include <cstdint>
#include <cstddef>

// ---------------- problem constants ----------------
#define V_SIZE 1024
#define H_SIZE 2048
#define F_SIZE 3072
#define T_STEPS 64
#define REC_F 0.8f
#define NCTAS 128

// ---------------- GEMM tiling ----------------
#define BM 128
#define BN 192
#define BK 64
#define KCHUNKS (F_SIZE / BK)   // 48
#define NTHREADS 384            // 12 warps: 2(M) x 6(N), warp tile 64x32
#define NSTAGES 3

// SMEM per stage: A(16K) Bh(24K) Bl(24K) = 64K
#define OFF_A  0
#define OFF_BH 16384
#define OFF_BL 40960
#define STAGE_BYTES 65536
// layout: [align slack 1K][hdr 1K: mbarriers][3 stages]
#define SMEM_BYTES (1024 + 1024 + NSTAGES * STAGE_BYTES)

// ---------------- device scratch ----------------
// Wh = fp16(W); Wl = fp16((W - Wh) * 64)  (scaled into fp16-normal range)
__device__ __half g_Wh[(size_t)F_SIZE * F_SIZE];
__device__ __half g_Wl[(size_t)F_SIZE * F_SIZE];
__device__ __half g_R[2][(size_t)V_SIZE * F_SIZE];
__device__ unsigned int g_bar;   // grid barrier counter (zeroed by split_w)

__device__ __forceinline__ uint32_t swz(uint32_t o) { return o ^ ((o >> 3) & 0x70u); }

#define LDM4(R_, A_)                                                              \
  asm volatile("ldmatrix.sync.aligned.m8n8.x4.shared.b16 {%0,%1,%2,%3}, [%4];"    \
               : "=r"((R_)[0]), "=r"((R_)[1]), "=r"((R_)[2]), "=r"((R_)[3])       \
               : "r"(A_))

#define MMA16816(C_, A_, B0_, B1_)                                                \
  asm volatile("mma.sync.aligned.m16n8k16.row.col.f32.f16.f16.f32 "               \
               "{%0,%1,%2,%3},{%4,%5,%6,%7},{%8,%9},{%0,%1,%2,%3};"               \
               : "+f"((C_)[0]), "+f"((C_)[1]), "+f"((C_)[2]), "+f"((C_)[3])       \
               : "r"((A_)[0]), "r"((A_)[1]), "r"((A_)[2]), "r"((A_)[3]),          \
                 "r"(B0_), "r"(B1_))

#define CP16(SO_, G_)                                                             \
  asm volatile("cp.async.cg.shared.global [%0], [%1], 16;" :: "r"(SO_), "l"(G_))

// .noinc: one arrival per thread when that thread's prior cp.asyncs complete.
#define CP_ASYNC_MBAR_ARRIVE_NOINC(mbar)                                          \
  asm volatile("cp.async.mbarrier.arrive.noinc.shared.b64 [%0];"                  \
               :: "r"((uint32_t)(mbar)) : "memory")

#define MBARRIER_INIT(mbar, count)                                                \
  asm volatile("mbarrier.init.shared.b64 [%0], %1;"                               \
               :: "r"((uint32_t)(mbar)), "r"((uint32_t)(count)) : "memory")
#define MBARRIER_ARRIVE(mbar)                                                     \
  asm volatile("mbarrier.arrive.shared.b64 _, [%0];"                              \
               :: "r"((uint32_t)(mbar)) : "memory")

__device__ __forceinline__ void mbar_wait_parity(uint32_t mbar, uint32_t parity) {
  uint32_t done;
  asm volatile("{\n\t.reg .pred p;\n\t"
               "mbarrier.try_wait.parity.acquire.cta.shared::cta.b64 p, [%1], %2;\n\t"
               "selp.b32 %0, 1, 0, p;\n\t}"
               : "=r"(done) : "r"(mbar), "r"(parity) : "memory");
  if (!done) {
    asm volatile("{\n\t.reg .pred P1;\n\t"
                 "WAIT_LOOP_%=:\n\t"
                 "mbarrier.try_wait.parity.acquire.cta.shared::cta.b64 P1, [%0], %1, 0x989680;\n\t"
                 "@P1 bra.uni WAIT_DONE_%=;\n\t"
                 "bra.uni WAIT_LOOP_%=;\n\t"
                 "WAIT_DONE_%=:\n\t}"
                 :: "r"(mbar), "r"(parity) : "memory");
  }
}

// fp16x2 constant 2^-6 (0x2400 per half)
#define HALF2_POW2_M6 0x24002400u

__device__ __forceinline__ uint32_t hmul2_scale(uint32_t a) {
  uint32_t r;
  asm volatile("mul.f16x2 %0, %1, %2;" : "=r"(r) : "r"(a), "r"(HALF2_POW2_M6));
  return r;
}

__device__ __forceinline__ float fast_tanh(float x) {
  float e = __expf(2.f * x);
  return 1.f - __fdividef(2.f, e + 1.f);
}

// -------- W split + barrier reset --------
__global__ void split_w_kernel(const float* __restrict__ W) {
  if (blockIdx.x == 0 && threadIdx.x == 0) g_bar = 0u;  // reset per replay
  const int n = F_SIZE * F_SIZE;
  for (int i = blockIdx.x * blockDim.x + threadIdx.x; i < n;
       i += gridDim.x * blockDim.x) {
    float w = W[i];
    __half h = __float2half(w);
    g_Wh[i] = h;
    g_Wl[i] = __float2half((w - __half2float(h)) * 64.f);
  }
}

// -------- step 0: R_0 = 0, epilogue-only --------
__global__ void step0_kernel(const float* __restrict__ X,
                             const float* __restrict__ b,
                             const float* __restrict__ lam) {
  const int n = V_SIZE * F_SIZE;
  for (int i = blockIdx.x * blockDim.x + threadIdx.x; i < n;
       i += gridDim.x * blockDim.x) {
    int c = i % F_SIZE;
    float l = lam[i];
    float u = l * b[c];
    if (c < V_SIZE) u += (1.f - l) * X[c];  // x_0
    g_R[1][i] = __float2half(tanhf(u));
  }
}

// -------- persistent kernel: all 63 recurrence steps, grid-synced --------
__global__ void __launch_bounds__(NTHREADS, 1)
frnn_persistent_kernel(const float* __restrict__ X, const float* __restrict__ b,
                       float* __restrict__ diag) {
  extern __shared__ unsigned char smem_raw[];
  uint32_t sbase = (uint32_t)__cvta_generic_to_shared(smem_raw);
  sbase = (sbase + 1023u) & ~1023u;  // SW128 swizzle wants 1KB alignment
  const uint32_t hdr = sbase;        // full[s]=hdr+s*8, empty[s]=hdr+64+s*8
  const uint32_t tiles = sbase + 1024;

  const int tid = threadIdx.x;
  const int lane = tid & 31;
  const int wid = tid >> 5;
  const int wm = (wid / 6) * 64;       // 0 / 64
  const int wn = (wid % 6) * 32;       // 0..160 step 32
  const int m0 = blockIdx.y * BM;
  const int n0 = blockIdx.x * BN;

  const __half* __restrict__ srcBh = g_Wh + (size_t)n0 * F_SIZE;
  const __half* __restrict__ srcBl = g_Wl + (size_t)n0 * F_SIZE;

  // --- init mbarriers once; parity arithmetic stays valid every step
  //     (48 chunks / 3 stages = 16 flips per stage per step, even) ---
  if (tid == 0) {
#pragma unroll
    for (int s = 0; s < NSTAGES; ++s) {
      MBARRIER_INIT(hdr + s * 8, NTHREADS);       // full[s]
      MBARRIER_INIT(hdr + 64 + s * 8, NTHREADS);  // empty[s]
    }
  }
  __syncthreads();

  const __half* srcA;  // captured by reference in lambdas, updated per step

  // --- async tile loader: 4096 x 16B chunks (A:1024, Bh:1536, Bl:1536) ---
  auto load_chunk = [&](int stage, int kc) {
    const uint32_t sb = tiles + (uint32_t)stage * STAGE_BYTES;
    const int koff = kc * BK;
#pragma unroll
    for (int it = 0; it < 11; ++it) {
      int i = tid + it * NTHREADS;
      if (it >= 10 && i >= 4096) break;
      const __half* gb;
      uint32_t stile;
      int j;
      if (i < 1024) {                       // A tile
        j = i;
        gb = srcA;
        stile = OFF_A;
      } else if (i < 2560) {                // Bh tile
        j = i - 1024;
        gb = srcBh;
        stile = OFF_BH;
      } else {                              // Bl tile
        j = i - 2560;
        gb = srcBl;
        stile = OFF_BL;
      }
      int r = j >> 3, c = j & 7;
      const void* g = gb + (size_t)r * F_SIZE + koff + c * 8;
      uint32_t so = sb + stile + swz((uint32_t)(r * 128 + c * 16));
      CP16(so, g);
    }
    CP_ASYNC_MBAR_ARRIVE_NOINC(hdr + stage * 8);  // full[stage]
  };

  float acc[4][4][4];

  // --- warp compute; arrives on empty[stage] right after the LAST LDSM ---
  auto compute = [&](int stage) {
    const uint32_t sb = tiles + (uint32_t)stage * STAGE_BYTES;
    const uint32_t aT = sb + OFF_A;
    const uint32_t bH = sb + OFF_BH;
    const uint32_t bL = sb + OFF_BL;
#pragma unroll
    for (int ks = 0; ks < 4; ++ks) {
      uint32_t ah[4][4], as[4][4], bh[2][4], bl[2][4];
#pragma unroll
      for (int mf = 0; mf < 4; ++mf) {
        uint32_t off = swz((uint32_t)((wm + mf * 16 + (lane & 15)) * 128 +
                                      (ks * 16 + ((lane >> 4) << 3)) * 2));
        LDM4(ah[mf], aT + off);
#pragma unroll
        for (int q = 0; q < 4; ++q) as[mf][q] = hmul2_scale(ah[mf][q]);
      }
#pragma unroll
      for (int nf2 = 0; nf2 < 2; ++nf2) {
        uint32_t off = swz((uint32_t)(
            (wn + nf2 * 16 + (lane & 7) + (((lane >> 4) & 1) << 3)) * 128 +
            (ks * 16 + ((lane >> 3) & 1) * 8) * 2));
        LDM4(bh[nf2], bH + off);
        LDM4(bl[nf2], bL + off);
      }
      if (ks == 3) MBARRIER_ARRIVE(hdr + 64 + stage * 8);  // empty[stage]
#pragma unroll
      for (int mf = 0; mf < 4; ++mf)
#pragma unroll
        for (int nf = 0; nf < 4; ++nf) {
          float* c = acc[mf][nf];
          uint32_t b0h = bh[nf >> 1][(nf & 1) * 2];
          uint32_t b1h = bh[nf >> 1][(nf & 1) * 2 + 1];
          uint32_t b0l = bl[nf >> 1][(nf & 1) * 2];
          uint32_t b1l = bl[nf >> 1][(nf & 1) * 2 + 1];
          MMA16816(c, ah[mf], b0h, b1h);  // Rh * Wh
          MMA16816(c, as[mf], b0l, b1l);  // (Rh*2^-6) * (Wl*2^6) = Rh * Wl
        }
    }
  };

  // ================= time loop =================
  for (int t = 1; t < T_STEPS; ++t) {
    srcA = g_R[t & 1] + (size_t)m0 * F_SIZE;
    __half* __restrict__ O = g_R[(t + 1) & 1];
    const float* __restrict__ Xr = X + (size_t)t * V_SIZE;

#pragma unroll
    for (int i = 0; i < 4; ++i)
#pragma unroll
      for (int j = 0; j < 4; ++j)
#pragma unroll
        for (int k = 0; k < 4; ++k) acc[i][j][k] = 0.f;

    // mainloop: 3-stage ring, mbarrier handshakes (parities cumulative-even
    // per step, so per-step arithmetic is unchanged; stages free at step
    // start because grid sync subsumed the empty handshake).
    load_chunk(0, 0);
    load_chunk(1, 1);
    for (int kc = 0; kc < KCHUNKS; ++kc) {
      const int c2 = kc + 2;
      if (c2 < KCHUNKS) {
        const int s2 = c2 % NSTAGES;
        if (c2 >= NSTAGES)
          mbar_wait_parity(hdr + 64 + s2 * 8, (uint32_t)((c2 / 3 + 1) & 1));
        load_chunk(s2, c2);
      }
      const int s = kc % NSTAGES;
      mbar_wait_parity(hdr + s * 8, (uint32_t)((kc / 3) & 1));
      compute(s);
    }

    // fused epilogue: lam from indices; U = lam*(C+b) + (1-lam)*x_t; R'=tanh
    const bool last = (t == T_STEPS - 1);
#pragma unroll
    for (int mf = 0; mf < 4; ++mf)
#pragma unroll
      for (int nf = 0; nf < 4; ++nf)
#pragma unroll
        for (int half = 0; half < 2; ++half) {
          int m = m0 + wm + mf * 16 + (lane >> 2) + half * 8;
          int n = n0 + wn + nf * 8 + 2 * (lane & 3);
          size_t idx = (size_t)m * F_SIZE + n;
          float c0 = acc[mf][nf][half * 2 + 0] + b[n];
          float c1 = acc[mf][nf][half * 2 + 1] + b[n + 1];
          bool vis = (n < V_SIZE);
          float l0 = (vis && n != m) ? REC_F : 1.0f;
          float l1 = (vis && (n + 1) != m) ? REC_F : 1.0f;
          float u0 = l0 * c0;
          float u1 = l1 * c1;
          if (vis) {
            u0 = fmaf(1.f - l0, Xr[n], u0);
            u1 = fmaf(1.f - l1, Xr[n + 1], u1);
          }
          if (last) {
            if (n == m) diag[m] = u0;
            if (n + 1 == m) diag[m] = u1;
          }
          __half2 hv;
          hv.x = __float2half(fast_tanh(u0));
          hv.y = __float2half(fast_tanh(u1));
          *reinterpret_cast<__half2*>(O + idx) = hv;
        }

    // ---- grid barrier (skip after final step) ----
    if (t < T_STEPS - 1) {
      __threadfence();   // release this thread's O writes GPU-wide
      __syncthreads();   // all threads of CTA fenced
      if (tid == 0) {
        atomicAdd(&g_bar, 1u);
        unsigned int target = (unsigned int)(NCTAS * t);
        unsigned int v;
        do {
          asm volatile("ld.acquire.gpu.u32 %0, [%1];"
                       : "=r"(v) : "l"(&g_bar));
          if (v < target) __nanosleep(64);
        } while (v < target);
      }
      __syncthreads();   // broadcast acquire to whole CTA
    }
  }
}

// ---------------- host launch ----------------
extern "C" void kernel_launch(void* const* d_in, const int* in_sizes, int n_in,
                              void* d_out, int out_size) {
  const float* X = (const float*)d_in[0];    // [T, V]
  const float* W = (const float*)d_in[1];    // [F, F]
  const float* b = (const float*)d_in[2];    // [F]
  const float* lam = (const float*)d_in[3];  // [V, F]
  float* out = (float*)d_out;                // [V]

  cudaFuncSetAttribute(frnn_persistent_kernel,
                       cudaFuncAttributeMaxDynamicSharedMemorySize, SMEM_BYTES);

  split_w_kernel<<<2048, 512>>>(W);          // also resets g_bar
  step0_kernel<<<2048, 512>>>(X, b, lam);

  dim3 grid(F_SIZE / BN, V_SIZE / BM);  // (16, 8) = 128 CTAs, one wave
  frnn_persistent_kernel<<<grid, NTHREADS, SMEM_BYTES>>>(X, b, out);
}

// round 11
// speedup vs baseline: 1.0340x; 1.0340x over previous
#include <cuda_runtime.h>
#include <cuda_fp16.h>
#include <cstdint>
#include <cstddef>

// ---------------- problem constants ----------------
#define V_SIZE 1024
#define H_SIZE 2048
#define F_SIZE 3072
#define T_STEPS 64
#define REC_F 0.8f

// ---------------- GEMM tiling ----------------
#define BM 128
#define BN 192
#define BK 64
#define KCHUNKS (F_SIZE / BK)   // 48
#define NTHREADS 384            // 12 warps: 2(M) x 6(N), warp tile 64x32
#define NSTAGES 3

// SMEM per stage: A(16K) Bh(24K) Bl(24K) = 64K
#define OFF_A  0
#define OFF_BH 16384
#define OFF_BL 40960
#define STAGE_BYTES 65536
// layout: [align slack 1K][hdr 1K: mbarriers][3 stages]
#define SMEM_BYTES (1024 + 1024 + NSTAGES * STAGE_BYTES)

// ---------------- device scratch ----------------
// Wh = fp16(W); Wl = fp16((W - Wh) * 64)  (scaled into fp16-normal range)
__device__ __half g_Wh[(size_t)F_SIZE * F_SIZE];
__device__ __half g_Wl[(size_t)F_SIZE * F_SIZE];
__device__ __half g_R[2][(size_t)V_SIZE * F_SIZE];

__device__ __forceinline__ uint32_t swz(uint32_t o) { return o ^ ((o >> 3) & 0x70u); }

#define LDM4(R_, A_)                                                              \
  asm volatile("ldmatrix.sync.aligned.m8n8.x4.shared.b16 {%0,%1,%2,%3}, [%4];"    \
               : "=r"((R_)[0]), "=r"((R_)[1]), "=r"((R_)[2]), "=r"((R_)[3])       \
               : "r"(A_))

#define MMA16816(C_, A_, B0_, B1_)                                                \
  asm volatile("mma.sync.aligned.m16n8k16.row.col.f32.f16.f16.f32 "               \
               "{%0,%1,%2,%3},{%4,%5,%6,%7},{%8,%9},{%0,%1,%2,%3};"               \
               : "+f"((C_)[0]), "+f"((C_)[1]), "+f"((C_)[2]), "+f"((C_)[3])       \
               : "r"((A_)[0]), "r"((A_)[1]), "r"((A_)[2]), "r"((A_)[3]),          \
                 "r"(B0_), "r"(B1_))

#define CP16(SO_, G_)                                                             \
  asm volatile("cp.async.cg.shared.global [%0], [%1], 16;" :: "r"(SO_), "l"(G_))

// .noinc: one arrival per thread when that thread's prior cp.asyncs complete.
#define CP_ASYNC_MBAR_ARRIVE_NOINC(mbar)                                          \
  asm volatile("cp.async.mbarrier.arrive.noinc.shared.b64 [%0];"                  \
               :: "r"((uint32_t)(mbar)) : "memory")

#define MBARRIER_INIT(mbar, count)                                                \
  asm volatile("mbarrier.init.shared.b64 [%0], %1;"                               \
               :: "r"((uint32_t)(mbar)), "r"((uint32_t)(count)) : "memory")
#define MBARRIER_ARRIVE(mbar)                                                     \
  asm volatile("mbarrier.arrive.shared.b64 _, [%0];"                              \
               :: "r"((uint32_t)(mbar)) : "memory")

__device__ __forceinline__ void mbar_wait_parity(uint32_t mbar, uint32_t parity) {
  uint32_t done;
  asm volatile("{\n\t.reg .pred p;\n\t"
               "mbarrier.try_wait.parity.acquire.cta.shared::cta.b64 p, [%1], %2;\n\t"
               "selp.b32 %0, 1, 0, p;\n\t}"
               : "=r"(done) : "r"(mbar), "r"(parity) : "memory");
  if (!done) {
    asm volatile("{\n\t.reg .pred P1;\n\t"
                 "WAIT_LOOP_%=:\n\t"
                 "mbarrier.try_wait.parity.acquire.cta.shared::cta.b64 P1, [%0], %1, 0x989680;\n\t"
                 "@P1 bra.uni WAIT_DONE_%=;\n\t"
                 "bra.uni WAIT_LOOP_%=;\n\t"
                 "WAIT_DONE_%=:\n\t}"
                 :: "r"(mbar), "r"(parity) : "memory");
  }
}

// fp16x2 constant 2^-6 (0x2400 per half)
#define HALF2_POW2_M6 0x24002400u

__device__ __forceinline__ uint32_t hmul2_scale(uint32_t a) {
  uint32_t r;
  asm volatile("mul.f16x2 %0, %1, %2;" : "=r"(r) : "r"(a), "r"(HALF2_POW2_M6));
  return r;
}

__device__ __forceinline__ float fast_tanh(float x) {
  float e = __expf(2.f * x);
  return 1.f - __fdividef(2.f, e + 1.f);
}

// -------- W split: fp32 -> fp16 hi + fp16 lo (lo pre-scaled by 2^6) --------
__global__ void split_w_kernel(const float* __restrict__ W) {
  const int n = F_SIZE * F_SIZE;
  for (int i = blockIdx.x * blockDim.x + threadIdx.x; i < n;
       i += gridDim.x * blockDim.x) {
    float w = W[i];
    __half h = __float2half(w);
    g_Wh[i] = h;
    g_Wl[i] = __float2half((w - __half2float(h)) * 64.f);
  }
}

// -------- step 0: R_0 = 0, epilogue-only --------
__global__ void step0_kernel(const float* __restrict__ X,
                             const float* __restrict__ b,
                             const float* __restrict__ lam) {
  const int n = V_SIZE * F_SIZE;
  for (int i = blockIdx.x * blockDim.x + threadIdx.x; i < n;
       i += gridDim.x * blockDim.x) {
    int c = i % F_SIZE;
    float l = lam[i];
    float u = l * b[c];
    if (c < V_SIZE) u += (1.f - l) * X[c];  // x_0
    g_R[1][i] = __float2half(tanhf(u));
  }
}

// -------- steps 1..62: C = R @ W^T (fp16 2-pass) + fused epilogue --------
__global__ void __launch_bounds__(NTHREADS, 1)
gemm_step_kernel(int t, const float* __restrict__ X, const float* __restrict__ b) {
  extern __shared__ unsigned char smem_raw[];
  uint32_t sbase = (uint32_t)__cvta_generic_to_shared(smem_raw);
  sbase = (sbase + 1023u) & ~1023u;  // SW128 swizzle wants 1KB alignment
  const uint32_t hdr = sbase;        // full[s]=hdr+s*8, empty[s]=hdr+64+s*8
  const uint32_t tiles = sbase + 1024;

  const __half* __restrict__ A = g_R[t & 1];
  __half* __restrict__ O = g_R[(t + 1) & 1];
  const float* __restrict__ Xr = X + (size_t)t * V_SIZE;

  const int tid = threadIdx.x;
  const int lane = tid & 31;
  const int wid = tid >> 5;
  const int wm = (wid / 6) * 64;       // 0 / 64
  const int wn = (wid % 6) * 32;       // 0..160 step 32
  const int m0 = blockIdx.y * BM;
  const int n0 = blockIdx.x * BN;

  const __half* __restrict__ srcA  = A + (size_t)m0 * F_SIZE;
  const __half* __restrict__ srcBh = g_Wh + (size_t)n0 * F_SIZE;
  const __half* __restrict__ srcBl = g_Wl + (size_t)n0 * F_SIZE;

  // --- init mbarriers (only __syncthreads in the kernel) ---
  if (tid == 0) {
#pragma unroll
    for (int s = 0; s < NSTAGES; ++s) {
      MBARRIER_INIT(hdr + s * 8, NTHREADS);       // full[s]
      MBARRIER_INIT(hdr + 64 + s * 8, NTHREADS);  // empty[s]
    }
  }
  __syncthreads();

  float acc[4][4][4];
#pragma unroll
  for (int i = 0; i < 4; ++i)
#pragma unroll
    for (int j = 0; j < 4; ++j)
#pragma unroll
      for (int k = 0; k < 4; ++k) acc[i][j][k] = 0.f;

  // --- async tile loader: 4096 x 16B chunks (A:1024, Bh:1536, Bl:1536) ---
  auto load_chunk = [&](int stage, int kc) {
    const uint32_t sb = tiles + (uint32_t)stage * STAGE_BYTES;
    const int koff = kc * BK;
#pragma unroll
    for (int it = 0; it < 11; ++it) {
      int i = tid + it * NTHREADS;
      if (it >= 10 && i >= 4096) break;
      const __half* gb;
      uint32_t stile;
      int j;
      if (i < 1024) {                       // A tile
        j = i;
        gb = srcA;
        stile = OFF_A;
      } else if (i < 2560) {                // Bh tile
        j = i - 1024;
        gb = srcBh;
        stile = OFF_BH;
      } else {                              // Bl tile
        j = i - 2560;
        gb = srcBl;
        stile = OFF_BL;
      }
      int r = j >> 3, c = j & 7;
      const void* g = gb + (size_t)r * F_SIZE + koff + c * 8;
      uint32_t so = sb + stile + swz((uint32_t)(r * 128 + c * 16));
      CP16(so, g);
    }
    CP_ASYNC_MBAR_ARRIVE_NOINC(hdr + stage * 8);  // full[stage]
  };

  // --- warp compute; arrives on empty[stage] right after the LAST LDSM ---
  auto compute = [&](int stage) {
    const uint32_t sb = tiles + (uint32_t)stage * STAGE_BYTES;
    const uint32_t aT = sb + OFF_A;
    const uint32_t bH = sb + OFF_BH;
    const uint32_t bL = sb + OFF_BL;
#pragma unroll
    for (int ks = 0; ks < 4; ++ks) {
      uint32_t ah[4][4], as[4][4], bh[2][4], bl[2][4];
#pragma unroll
      for (int mf = 0; mf < 4; ++mf) {
        uint32_t off = swz((uint32_t)((wm + mf * 16 + (lane & 15)) * 128 +
                                      (ks * 16 + ((lane >> 4) << 3)) * 2));
        LDM4(ah[mf], aT + off);
#pragma unroll
        for (int q = 0; q < 4; ++q) as[mf][q] = hmul2_scale(ah[mf][q]);
      }
#pragma unroll
      for (int nf2 = 0; nf2 < 2; ++nf2) {
        uint32_t off = swz((uint32_t)(
            (wn + nf2 * 16 + (lane & 7) + (((lane >> 4) & 1) << 3)) * 128 +
            (ks * 16 + ((lane >> 3) & 1) * 8) * 2));
        LDM4(bh[nf2], bH + off);
        LDM4(bl[nf2], bL + off);
      }
      if (ks == 3) {
        // all of this thread's reads from `stage` are done (fragments in regs)
        MBARRIER_ARRIVE(hdr + 64 + stage * 8);  // empty[stage]
      }
#pragma unroll
      for (int mf = 0; mf < 4; ++mf)
#pragma unroll
        for (int nf = 0; nf < 4; ++nf) {
          float* c = acc[mf][nf];
          uint32_t b0h = bh[nf >> 1][(nf & 1) * 2];
          uint32_t b1h = bh[nf >> 1][(nf & 1) * 2 + 1];
          uint32_t b0l = bl[nf >> 1][(nf & 1) * 2];
          uint32_t b1l = bl[nf >> 1][(nf & 1) * 2 + 1];
          MMA16816(c, ah[mf], b0h, b1h);  // Rh * Wh
          MMA16816(c, as[mf], b0l, b1l);  // (Rh*2^-6) * (Wl*2^6) = Rh * Wl
        }
    }
  };

  // --- mainloop: 3-stage ring, mbarrier handshakes, no block barrier ---
  // chunk c -> stage c%3; full parity for chunk c: (c/3)&1;
  // empty parity loader waits before loading chunk c (c>=3): ((c/3)+1)&1.
  load_chunk(0, 0);
  load_chunk(1, 1);
  for (int kc = 0; kc < KCHUNKS; ++kc) {
    const int c2 = kc + 2;
    if (c2 < KCHUNKS) {
      const int s2 = c2 % NSTAGES;
      if (c2 >= NSTAGES)
        mbar_wait_parity(hdr + 64 + s2 * 8, (uint32_t)((c2 / 3 + 1) & 1));
      load_chunk(s2, c2);
    }
    const int s = kc % NSTAGES;
    mbar_wait_parity(hdr + s * 8, (uint32_t)((kc / 3) & 1));
    compute(s);
  }

  // --- fused epilogue: lam from indices; U = lam*(C+b) + (1-lam)*x_t; tanh ---
  // (no diag branch here: the final step is handled by diag_kernel)
#pragma unroll
  for (int mf = 0; mf < 4; ++mf)
#pragma unroll
    for (int nf = 0; nf < 4; ++nf)
#pragma unroll
      for (int half = 0; half < 2; ++half) {
        int m = m0 + wm + mf * 16 + (lane >> 2) + half * 8;
        int n = n0 + wn + nf * 8 + 2 * (lane & 3);
        size_t idx = (size_t)m * F_SIZE + n;
        float c0 = acc[mf][nf][half * 2 + 0] + b[n];
        float c1 = acc[mf][nf][half * 2 + 1] + b[n + 1];
        bool vis = (n < V_SIZE);  // n even, V even -> pair stays inside block
        float l0 = (vis && n != m) ? REC_F : 1.0f;
        float l1 = (vis && (n + 1) != m) ? REC_F : 1.0f;
        float u0 = l0 * c0;
        float u1 = l1 * c1;
        if (vis) {
          u0 = fmaf(1.f - l0, Xr[n], u0);
          u1 = fmaf(1.f - l1, Xr[n + 1], u1);
        }
        __half2 hv;
        hv.x = __float2half(fast_tanh(u0));
        hv.y = __float2half(fast_tanh(u1));
        *reinterpret_cast<__half2*>(O + idx) = hv;
      }
}

// -------- final step (t=63): output needs only diag(U[:, :V]) --------
// lam[i,i] = 1  =>  diag[i] = dot(R_63[i,:], W[i,:]) + b[i]   (fp32 W, exact)
// R_63 lives in g_R[1] (written by step t=62 into g_R[(62+1)&1]).
__global__ void __launch_bounds__(256, 1)
diag_kernel(const float* __restrict__ W, const float* __restrict__ b,
            float* __restrict__ diag) {
  const int lane = threadIdx.x & 31;
  const int row = blockIdx.x * 8 + (threadIdx.x >> 5);  // one warp per row
  if (row >= V_SIZE) return;

  const __half* __restrict__ r = g_R[1] + (size_t)row * F_SIZE;
  const float* __restrict__ w = W + (size_t)row * F_SIZE;

  float acc = 0.f;
#pragma unroll
  for (int k0 = lane * 4; k0 < F_SIZE; k0 += 128) {
    // 4 R halves (8B) + 4 W floats (16B), fp32 FMA
    __half2 rv01 = *reinterpret_cast<const __half2*>(r + k0);
    __half2 rv23 = *reinterpret_cast<const __half2*>(r + k0 + 2);
    float4 wv = *reinterpret_cast<const float4*>(w + k0);
    float2 f01 = __half22float2(rv01);
    float2 f23 = __half22float2(rv23);
    acc = fmaf(f01.x, wv.x, acc);
    acc = fmaf(f01.y, wv.y, acc);
    acc = fmaf(f23.x, wv.z, acc);
    acc = fmaf(f23.y, wv.w, acc);
  }
#pragma unroll
  for (int off = 16; off > 0; off >>= 1)
    acc += __shfl_xor_sync(0xFFFFFFFFu, acc, off);
  if (lane == 0) diag[row] = acc + b[row];
}

// ---------------- host launch ----------------
extern "C" void kernel_launch(void* const* d_in, const int* in_sizes, int n_in,
                              void* d_out, int out_size) {
  const float* X = (const float*)d_in[0];    // [T, V]
  const float* W = (const float*)d_in[1];    // [F, F]
  const float* b = (const float*)d_in[2];    // [F]
  const float* lam = (const float*)d_in[3];  // [V, F]
  float* out = (float*)d_out;                // [V]

  cudaFuncSetAttribute(gemm_step_kernel,
                       cudaFuncAttributeMaxDynamicSharedMemorySize, SMEM_BYTES);

  split_w_kernel<<<2048, 512>>>(W);
  step0_kernel<<<2048, 512>>>(X, b, lam);

  dim3 grid(F_SIZE / BN, V_SIZE / BM);  // (16, 8) = 128 CTAs, single wave
  for (int t = 1; t < T_STEPS - 1; ++t) {  // t = 1..62
    gemm_step_kernel<<<grid, NTHREADS, SMEM_BYTES>>>(t, X, b);
  }
  diag_kernel<<<V_SIZE / 8, 256>>>(W, b, out);  // t = 63, diag only
}

// round 12
// speedup vs baseline: 1.0606x; 1.0258x over previous
#include <cuda_runtime.h>
#include <cuda_fp16.h>
#include <cstdint>
#include <cstddef>

// ---------------- problem constants ----------------
#define V_SIZE 1024
#define H_SIZE 2048
#define F_SIZE 3072
#define T_STEPS 64
#define REC_F 0.8f

// ---------------- GEMM tiling (dual-CTA-per-SM config) ----------------
#define BM 128
#define BN 96
#define BK 64
#define KCHUNKS (F_SIZE / BK)   // 48
#define NTHREADS 128            // 4 warps: 2(M) x 2(N), warp tile 64x48
#define NSTAGES 2

// SMEM per stage: A(16K) Bh(12K) Bl(12K) = 40K
#define OFF_A  0
#define OFF_BH 16384
#define OFF_BL 28672
#define STAGE_BYTES 40960
// layout: [align slack 1K][hdr 1K: mbarriers][2 stages] = 84KB -> 2 CTAs/SM
#define SMEM_BYTES (1024 + 1024 + NSTAGES * STAGE_BYTES)

// ---------------- device scratch ----------------
// Wh = fp16(W); Wl = fp16((W - Wh) * 64)  (scaled into fp16-normal range)
__device__ __half g_Wh[(size_t)F_SIZE * F_SIZE];
__device__ __half g_Wl[(size_t)F_SIZE * F_SIZE];
__device__ __half g_R[2][(size_t)V_SIZE * F_SIZE];

__device__ __forceinline__ uint32_t swz(uint32_t o) { return o ^ ((o >> 3) & 0x70u); }

#define LDM4(R_, A_)                                                              \
  asm volatile("ldmatrix.sync.aligned.m8n8.x4.shared.b16 {%0,%1,%2,%3}, [%4];"    \
               : "=r"((R_)[0]), "=r"((R_)[1]), "=r"((R_)[2]), "=r"((R_)[3])       \
               : "r"(A_))

#define MMA16816(C_, A_, B0_, B1_)                                                \
  asm volatile("mma.sync.aligned.m16n8k16.row.col.f32.f16.f16.f32 "               \
               "{%0,%1,%2,%3},{%4,%5,%6,%7},{%8,%9},{%0,%1,%2,%3};"               \
               : "+f"((C_)[0]), "+f"((C_)[1]), "+f"((C_)[2]), "+f"((C_)[3])       \
               : "r"((A_)[0]), "r"((A_)[1]), "r"((A_)[2]), "r"((A_)[3]),          \
                 "r"(B0_), "r"(B1_))

#define CP16(SO_, G_)                                                             \
  asm volatile("cp.async.cg.shared.global [%0], [%1], 16;" :: "r"(SO_), "l"(G_))

// .noinc: one arrival per thread when that thread's prior cp.asyncs complete.
#define CP_ASYNC_MBAR_ARRIVE_NOINC(mbar)                                          \
  asm volatile("cp.async.mbarrier.arrive.noinc.shared.b64 [%0];"                  \
               :: "r"((uint32_t)(mbar)) : "memory")

#define MBARRIER_INIT(mbar, count)                                                \
  asm volatile("mbarrier.init.shared.b64 [%0], %1;"                               \
               :: "r"((uint32_t)(mbar)), "r"((uint32_t)(count)) : "memory")
#define MBARRIER_ARRIVE(mbar)                                                     \
  asm volatile("mbarrier.arrive.shared.b64 _, [%0];"                              \
               :: "r"((uint32_t)(mbar)) : "memory")

__device__ __forceinline__ void mbar_wait_parity(uint32_t mbar, uint32_t parity) {
  uint32_t done;
  asm volatile("{\n\t.reg .pred p;\n\t"
               "mbarrier.try_wait.parity.acquire.cta.shared::cta.b64 p, [%1], %2;\n\t"
               "selp.b32 %0, 1, 0, p;\n\t}"
               : "=r"(done) : "r"(mbar), "r"(parity) : "memory");
  if (!done) {
    asm volatile("{\n\t.reg .pred P1;\n\t"
                 "WAIT_LOOP_%=:\n\t"
                 "mbarrier.try_wait.parity.acquire.cta.shared::cta.b64 P1, [%0], %1, 0x989680;\n\t"
                 "@P1 bra.uni WAIT_DONE_%=;\n\t"
                 "bra.uni WAIT_LOOP_%=;\n\t"
                 "WAIT_DONE_%=:\n\t}"
                 :: "r"(mbar), "r"(parity) : "memory");
  }
}

// fp16x2 constant 2^-6 (0x2400 per half)
#define HALF2_POW2_M6 0x24002400u

__device__ __forceinline__ uint32_t hmul2_scale(uint32_t a) {
  uint32_t r;
  asm volatile("mul.f16x2 %0, %1, %2;" : "=r"(r) : "r"(a), "r"(HALF2_POW2_M6));
  return r;
}

__device__ __forceinline__ float fast_tanh(float x) {
  float e = __expf(2.f * x);
  return 1.f - __fdividef(2.f, e + 1.f);
}

// -------- W split: fp32 -> fp16 hi + fp16 lo (lo pre-scaled by 2^6) --------
__global__ void split_w_kernel(const float* __restrict__ W) {
  const int n = F_SIZE * F_SIZE;
  for (int i = blockIdx.x * blockDim.x + threadIdx.x; i < n;
       i += gridDim.x * blockDim.x) {
    float w = W[i];
    __half h = __float2half(w);
    g_Wh[i] = h;
    g_Wl[i] = __float2half((w - __half2float(h)) * 64.f);
  }
}

// -------- step 0: R_0 = 0, epilogue-only --------
__global__ void step0_kernel(const float* __restrict__ X,
                             const float* __restrict__ b,
                             const float* __restrict__ lam) {
  const int n = V_SIZE * F_SIZE;
  for (int i = blockIdx.x * blockDim.x + threadIdx.x; i < n;
       i += gridDim.x * blockDim.x) {
    int c = i % F_SIZE;
    float l = lam[i];
    float u = l * b[c];
    if (c < V_SIZE) u += (1.f - l) * X[c];  // x_0
    g_R[1][i] = __float2half(tanhf(u));
  }
}

// -------- steps 1..62: C = R @ W^T (fp16 2-pass) + fused epilogue --------
__global__ void __launch_bounds__(NTHREADS, 2)
gemm_step_kernel(int t, const float* __restrict__ X, const float* __restrict__ b) {
  extern __shared__ unsigned char smem_raw[];
  uint32_t sbase = (uint32_t)__cvta_generic_to_shared(smem_raw);
  sbase = (sbase + 1023u) & ~1023u;  // SW128 swizzle wants 1KB alignment
  const uint32_t hdr = sbase;        // full[s]=hdr+s*8, empty[s]=hdr+64+s*8
  const uint32_t tiles = sbase + 1024;

  const __half* __restrict__ A = g_R[t & 1];
  __half* __restrict__ O = g_R[(t + 1) & 1];
  const float* __restrict__ Xr = X + (size_t)t * V_SIZE;

  const int tid = threadIdx.x;
  const int lane = tid & 31;
  const int wid = tid >> 5;
  const int wm = (wid >> 1) * 64;      // 0 / 64
  const int wn = (wid & 1) * 48;       // 0 / 48
  const int m0 = blockIdx.y * BM;
  const int n0 = blockIdx.x * BN;

  const __half* __restrict__ srcA  = A + (size_t)m0 * F_SIZE;
  const __half* __restrict__ srcBh = g_Wh + (size_t)n0 * F_SIZE;
  const __half* __restrict__ srcBl = g_Wl + (size_t)n0 * F_SIZE;

  // --- init mbarriers (only __syncthreads in the kernel) ---
  if (tid == 0) {
#pragma unroll
    for (int s = 0; s < NSTAGES; ++s) {
      MBARRIER_INIT(hdr + s * 8, NTHREADS);       // full[s]
      MBARRIER_INIT(hdr + 64 + s * 8, NTHREADS);  // empty[s]
    }
  }
  __syncthreads();

  float acc[4][6][4];
#pragma unroll
  for (int i = 0; i < 4; ++i)
#pragma unroll
    for (int j = 0; j < 6; ++j)
#pragma unroll
      for (int k = 0; k < 4; ++k) acc[i][j][k] = 0.f;

  // --- async tile loader: 2560 x 16B chunks (A:1024, Bh:768, Bl:768) ---
  // 128 threads x 20 iterations, exact cover.
  auto load_chunk = [&](int stage, int kc) {
    const uint32_t sb = tiles + (uint32_t)stage * STAGE_BYTES;
    const int koff = kc * BK;
#pragma unroll
    for (int it = 0; it < 20; ++it) {
      int i = tid + it * NTHREADS;
      const __half* gb;
      uint32_t stile;
      int j;
      if (i < 1024) {                       // A tile (128 rows)
        j = i;
        gb = srcA;
        stile = OFF_A;
      } else if (i < 1792) {                // Bh tile (96 rows)
        j = i - 1024;
        gb = srcBh;
        stile = OFF_BH;
      } else {                              // Bl tile (96 rows)
        j = i - 1792;
        gb = srcBl;
        stile = OFF_BL;
      }
      int r = j >> 3, c = j & 7;
      const void* g = gb + (size_t)r * F_SIZE + koff + c * 8;
      uint32_t so = sb + stile + swz((uint32_t)(r * 128 + c * 16));
      CP16(so, g);
    }
    CP_ASYNC_MBAR_ARRIVE_NOINC(hdr + stage * 8);  // full[stage]
  };

  // --- warp compute (64x48 tile); arrives on empty[stage] after last LDSM ---
  auto compute = [&](int stage) {
    const uint32_t sb = tiles + (uint32_t)stage * STAGE_BYTES;
    const uint32_t aT = sb + OFF_A;
    const uint32_t bH = sb + OFF_BH;
    const uint32_t bL = sb + OFF_BL;
#pragma unroll
    for (int ks = 0; ks < 4; ++ks) {
      uint32_t ah[4][4], as[4][4], bh[3][4], bl[3][4];
#pragma unroll
      for (int mf = 0; mf < 4; ++mf) {
        uint32_t off = swz((uint32_t)((wm + mf * 16 + (lane & 15)) * 128 +
                                      (ks * 16 + ((lane >> 4) << 3)) * 2));
        LDM4(ah[mf], aT + off);
#pragma unroll
        for (int q = 0; q < 4; ++q) as[mf][q] = hmul2_scale(ah[mf][q]);
      }
#pragma unroll
      for (int nf2 = 0; nf2 < 3; ++nf2) {
        uint32_t off = swz((uint32_t)(
            (wn + nf2 * 16 + (lane & 7) + (((lane >> 4) & 1) << 3)) * 128 +
            (ks * 16 + ((lane >> 3) & 1) * 8) * 2));
        LDM4(bh[nf2], bH + off);
        LDM4(bl[nf2], bL + off);
      }
      if (ks == 3) {
        // all of this thread's reads from `stage` done (fragments in regs)
        MBARRIER_ARRIVE(hdr + 64 + stage * 8);  // empty[stage]
      }
#pragma unroll
      for (int mf = 0; mf < 4; ++mf)
#pragma unroll
        for (int nf = 0; nf < 6; ++nf) {
          float* c = acc[mf][nf];
          uint32_t b0h = bh[nf >> 1][(nf & 1) * 2];
          uint32_t b1h = bh[nf >> 1][(nf & 1) * 2 + 1];
          uint32_t b0l = bl[nf >> 1][(nf & 1) * 2];
          uint32_t b1l = bl[nf >> 1][(nf & 1) * 2 + 1];
          MMA16816(c, ah[mf], b0h, b1h);  // Rh * Wh
          MMA16816(c, as[mf], b0l, b1l);  // (Rh*2^-6) * (Wl*2^6) = Rh * Wl
        }
    }
  };

  // --- mainloop: 2-stage ring; compute-then-load order (2-stage safe) ---
  // chunk c -> stage c&1, use j=c>>1; full parity j&1; empty parity j&1.
  load_chunk(0, 0);
  load_chunk(1, 1);
  for (int kc = 0; kc < KCHUNKS; ++kc) {
    const int s = kc & 1;
    const uint32_t j = (uint32_t)(kc >> 1);
    mbar_wait_parity(hdr + s * 8, j & 1);      // full[s] for chunk kc
    compute(s);                                 // empty-arrive inside (ks==3)
    if (kc + 2 < KCHUNKS) {
      mbar_wait_parity(hdr + 64 + s * 8, j & 1);  // all warps done reading s
      load_chunk(s, kc + 2);
    }
  }

  // --- fused epilogue: lam from indices; U = lam*(C+b) + (1-lam)*x_t; tanh ---
#pragma unroll
  for (int mf = 0; mf < 4; ++mf)
#pragma unroll
    for (int nf = 0; nf < 6; ++nf)
#pragma unroll
      for (int half = 0; half < 2; ++half) {
        int m = m0 + wm + mf * 16 + (lane >> 2) + half * 8;
        int n = n0 + wn + nf * 8 + 2 * (lane & 3);
        size_t idx = (size_t)m * F_SIZE + n;
        float c0 = acc[mf][nf][half * 2 + 0] + b[n];
        float c1 = acc[mf][nf][half * 2 + 1] + b[n + 1];
        bool vis = (n < V_SIZE);  // n even, V even -> pair stays inside block
        float l0 = (vis && n != m) ? REC_F : 1.0f;
        float l1 = (vis && (n + 1) != m) ? REC_F : 1.0f;
        float u0 = l0 * c0;
        float u1 = l1 * c1;
        if (vis) {
          u0 = fmaf(1.f - l0, Xr[n], u0);
          u1 = fmaf(1.f - l1, Xr[n + 1], u1);
        }
        __half2 hv;
        hv.x = __float2half(fast_tanh(u0));
        hv.y = __float2half(fast_tanh(u1));
        *reinterpret_cast<__half2*>(O + idx) = hv;
      }
}

// -------- final step (t=63): output needs only diag(U[:, :V]) --------
// lam[i,i] = 1  =>  diag[i] = dot(R_63[i,:], W[i,:]) + b[i]   (fp32 W, exact)
__global__ void __launch_bounds__(256, 1)
diag_kernel(const float* __restrict__ W, const float* __restrict__ b,
            float* __restrict__ diag) {
  const int lane = threadIdx.x & 31;
  const int row = blockIdx.x * 8 + (threadIdx.x >> 5);  // one warp per row
  if (row >= V_SIZE) return;

  const __half* __restrict__ r = g_R[1] + (size_t)row * F_SIZE;
  const float* __restrict__ w = W + (size_t)row * F_SIZE;

  float acc = 0.f;
#pragma unroll
  for (int k0 = lane * 4; k0 < F_SIZE; k0 += 128) {
    __half2 rv01 = *reinterpret_cast<const __half2*>(r + k0);
    __half2 rv23 = *reinterpret_cast<const __half2*>(r + k0 + 2);
    float4 wv = *reinterpret_cast<const float4*>(w + k0);
    float2 f01 = __half22float2(rv01);
    float2 f23 = __half22float2(rv23);
    acc = fmaf(f01.x, wv.x, acc);
    acc = fmaf(f01.y, wv.y, acc);
    acc = fmaf(f23.x, wv.z, acc);
    acc = fmaf(f23.y, wv.w, acc);
  }
#pragma unroll
  for (int off = 16; off > 0; off >>= 1)
    acc += __shfl_xor_sync(0xFFFFFFFFu, acc, off);
  if (lane == 0) diag[row] = acc + b[row];
}

// ---------------- host launch ----------------
extern "C" void kernel_launch(void* const* d_in, const int* in_sizes, int n_in,
                              void* d_out, int out_size) {
  const float* X = (const float*)d_in[0];    // [T, V]
  const float* W = (const float*)d_in[1];    // [F, F]
  const float* b = (const float*)d_in[2];    // [F]
  const float* lam = (const float*)d_in[3];  // [V, F]
  float* out = (float*)d_out;                // [V]

  cudaFuncSetAttribute(gemm_step_kernel,
                       cudaFuncAttributeMaxDynamicSharedMemorySize, SMEM_BYTES);

  split_w_kernel<<<2048, 512>>>(W);
  step0_kernel<<<2048, 512>>>(X, b, lam);

  dim3 grid(F_SIZE / BN, V_SIZE / BM);  // (32, 8) = 256 CTAs, 2 per SM
  for (int t = 1; t < T_STEPS - 1; ++t) {  // t = 1..62
    gemm_step_kernel<<<grid, NTHREADS, SMEM_BYTES>>>(t, X, b);
  }
  diag_kernel<<<V_SIZE / 8, 256>>>(W, b, out);  // t = 63, diag only
}